// round 1
// baseline (speedup 1.0000x reference)
#include <cuda_runtime.h>
#include <cuda_bf16.h>

#define T_LEN 2048
#define KP    17
#define HID   64
#define B_SZ  32
#define NCLS  10
#define TILE_T 16
#define ROWS  (TILE_T * KP)        // 272
#define NT    (T_LEN / TILE_T)     // 128
#define ZW    68

typedef unsigned long long ull;

// Scratch (allocation-free rule: __device__ globals)
__device__ float g_buf0[(size_t)B_SZ * T_LEN * KP * HID];
__device__ float g_buf1[(size_t)B_SZ * T_LEN * KP * HID];
__device__ float g_Wf[3][3 * HID * HID];   // [blk][(tau*CIN + j)*64 + o]
__device__ float g_beta[3][HID];
__device__ float g_part[(size_t)B_SZ * NT * HID];

__device__ __forceinline__ void fma2(ull& d, ull a, ull b) {
    asm("fma.rn.f32x2 %0, %1, %2, %3;" : "=l"(d) : "l"(a), "l"(b), "l"(d));
}
__device__ __forceinline__ ull pack2(float x, float y) {
    ull r;
    asm("mov.b64 %0, {%1, %2};" : "=l"(r) : "f"(x), "f"(y));
    return r;
}
__device__ __forceinline__ float2 unpack2(ull v) {
    float2 r;
    asm("mov.b64 {%0, %1}, %2;" : "=f"(r.x), "=f"(r.y) : "l"(v));
    return r;
}

// ---------------------------------------------------------------------------
// Weight preprocessing: Wf[blk][tau][j][o] = (sum_i gw[j,i] * tw[o,i,tau]) * bn_inv[o]
// beta[blk][o] = bb - bs*bm/sqrt(bv+eps)
// ---------------------------------------------------------------------------
__global__ void prep_kernel(const float* __restrict__ gw0, const float* __restrict__ gw1,
                            const float* __restrict__ gw2, const float* __restrict__ tcn,
                            const float* __restrict__ bs, const float* __restrict__ bb,
                            const float* __restrict__ bm, const float* __restrict__ bv)
{
    int blk = blockIdx.x;      // 0..2
    int tau = blockIdx.y;      // 0..2
    int o   = threadIdx.x;     // 0..63
    const float* gw = (blk == 0) ? gw0 : ((blk == 1) ? gw1 : gw2);
    int CIN = (blk == 0) ? 3 : 64;
    float rstd = rsqrtf(bv[blk*64 + o] + 1e-5f);
    float inv  = bs[blk*64 + o] * rstd;
    if (tau == 0)
        g_beta[blk][o] = bb[blk*64 + o] - bs[blk*64 + o] * bm[blk*64 + o] * rstd;
    const float* tw = tcn + (size_t)blk * HID * HID * 3;   // [o][i][tau]
    for (int j = 0; j < CIN; j++) {
        float s = 0.f;
        for (int i = 0; i < HID; i++)
            s += gw[j*HID + i] * tw[(o*HID + i)*3 + tau];
        g_Wf[blk][(tau*CIN + j)*HID + o] = s * inv;
    }
}

// ---------------------------------------------------------------------------
// Fused ST-GCN block: temporal-conv GEMM (f32x2 packed) + graph conv + BN bias
// + ReLU + residual, optional pooled partial sums.
// Layout: [b][t][k][c], c contiguous.
// ---------------------------------------------------------------------------
template<int CIN, int D, bool RES, bool ACC>
__global__ __launch_bounds__(288)
void stblock(const float* __restrict__ xin, float* __restrict__ yout,
             const float* __restrict__ adjg, int blk)
{
    constexpr int NTH  = (TILE_T + 2*D) * KP;            // halo'd tile rows
    constexpr int XS   = ((CIN*NTH + 3) & ~3);           // 16B-aligned size
    constexpr int WTOT = 3 * CIN * HID;

    extern __shared__ float sm[];
    float* xsT  = sm;                    // [CIN][NTH] transposed x tile
    float* Ws   = sm + XS;               // [3*CIN][64]
    float* zs   = Ws + WTOT;             // [ROWS][ZW]
    float* sadj = zs + ROWS * ZW;        // [17*17] (+3 pad)
    float* sbet = sadj + 292;            // [64]

    const int tid = threadIdx.x;
    const int b   = blockIdx.y;
    const int t0  = blockIdx.x * TILE_T;

    // ---- load weights / adj / bias ----
    const float* wf = g_Wf[blk];
    for (int u = tid; u < WTOT; u += 288) Ws[u] = wf[u];
    for (int u = tid; u < KP*KP; u += 288) sadj[u] = adjg[u];
    if (tid < HID) sbet[tid] = g_beta[blk][tid];

    // ---- load x tile, transposed to [c][plane], zero-padded in t ----
    const float* xb = xin + (size_t)b * T_LEN * KP * CIN;
    if (CIN == 64) {
        for (int u = tid; u < NTH*16; u += 288) {
            int p = u >> 4, cq = u & 15;
            int tl = p / KP, v = p - tl*KP;
            int tg = t0 + tl - D;
            float4 val = make_float4(0.f, 0.f, 0.f, 0.f);
            if (tg >= 0 && tg < T_LEN)
                val = *(const float4*)(xb + ((size_t)tg*KP + v)*64 + cq*4);
            int c = cq * 4;
            xsT[(c+0)*NTH + p] = val.x;
            xsT[(c+1)*NTH + p] = val.y;
            xsT[(c+2)*NTH + p] = val.z;
            xsT[(c+3)*NTH + p] = val.w;
        }
    } else {
        for (int u = tid; u < NTH*CIN; u += 288) {
            int p = u / CIN, c = u - p*CIN;
            int tl = p / KP, v = p - tl*KP;
            int tg = t0 + tl - D;
            float val = 0.f;
            if (tg >= 0 && tg < T_LEN)
                val = xb[((size_t)tg*KP + v)*CIN + c];
            xsT[c*NTH + p] = val;
        }
    }
    __syncthreads();

    const int mg = tid >> 2;          // row-group 0..67
    const int ng = tid & 3;           // col-group 0..3
    const int r0 = mg * 4;
    const bool active = (tid < ROWS);

    // ---- temporal/channel conv GEMM: z[r][o] = sum_{tau,j} x[r + tau*17*D][j] * Wf[tau*CIN+j][o]
    if (active) {
        ull acc[4][8];
        #pragma unroll
        for (int i = 0; i < 4; i++)
            #pragma unroll
            for (int q = 0; q < 8; q++) acc[i][q] = 0ull;

        #pragma unroll
        for (int tau = 0; tau < 3; tau++) {
            const float* xpl = xsT + tau*(KP*D) + r0;
            const float* wro = Ws + tau*CIN*HID + ng*4;
            #pragma unroll 4
            for (int j = 0; j < CIN; j++) {
                const float* xp = xpl + j*NTH;
                ull xa0 = pack2(xp[0], xp[0]);
                ull xa1 = pack2(xp[1], xp[1]);
                ull xa2 = pack2(xp[2], xp[2]);
                ull xa3 = pack2(xp[3], xp[3]);
                const float* wr = wro + j*HID;
                #pragma unroll
                for (int q = 0; q < 4; q++) {
                    ulonglong2 w = *(const ulonglong2*)(wr + q*16);
                    fma2(acc[0][2*q], xa0, w.x); fma2(acc[0][2*q+1], xa0, w.y);
                    fma2(acc[1][2*q], xa1, w.x); fma2(acc[1][2*q+1], xa1, w.y);
                    fma2(acc[2][2*q], xa2, w.x); fma2(acc[2][2*q+1], xa2, w.y);
                    fma2(acc[3][2*q], xa3, w.x); fma2(acc[3][2*q+1], xa3, w.y);
                }
            }
        }
        // z -> smem
        #pragma unroll
        for (int i = 0; i < 4; i++) {
            #pragma unroll
            for (int q = 0; q < 4; q++) {
                float2 lo = unpack2(acc[i][2*q]);
                float2 hi = unpack2(acc[i][2*q+1]);
                *(float4*)(zs + (r0+i)*ZW + q*16 + ng*4) = make_float4(lo.x, lo.y, hi.x, hi.y);
            }
        }
    }
    __syncthreads();

    // ---- graph conv over keypoints + bias + relu + residual + store ----
    if (active) {
        float csum[16];
        if (ACC) {
            #pragma unroll
            for (int u = 0; u < 16; u++) csum[u] = 0.f;
        }
        #pragma unroll
        for (int i = 0; i < 4; i++) {
            int r  = r0 + i;
            int t  = r / KP;
            int kk = r - t*KP;
            ull res[8];
            #pragma unroll
            for (int q = 0; q < 4; q++) {
                float4 bq = *(const float4*)(sbet + q*16 + ng*4);
                res[2*q]   = pack2(bq.x, bq.y);
                res[2*q+1] = pack2(bq.z, bq.w);
            }
            const float* zb = zs + t*KP*ZW + ng*4;
            #pragma unroll 1
            for (int v = 0; v < KP; v++) {
                float av = sadj[v*KP + kk];
                ull a2 = pack2(av, av);
                const float* zp = zb + v*ZW;
                #pragma unroll
                for (int q = 0; q < 4; q++) {
                    ulonglong2 zz = *(const ulonglong2*)(zp + q*16);
                    fma2(res[2*q],   a2, zz.x);
                    fma2(res[2*q+1], a2, zz.y);
                }
            }
            float* op = yout + (((size_t)b*T_LEN + (t0 + t))*KP + kk)*HID;
            int p = (t + D)*KP + kk;
            #pragma unroll
            for (int q = 0; q < 4; q++) {
                float2 lo = unpack2(res[2*q]);
                float2 hi = unpack2(res[2*q+1]);
                int c = q*16 + ng*4;
                float4 o;
                o.x = fmaxf(lo.x, 0.f);
                o.y = fmaxf(lo.y, 0.f);
                o.z = fmaxf(hi.x, 0.f);
                o.w = fmaxf(hi.y, 0.f);
                if (RES) {
                    o.x += xsT[(c+0)*NTH + p];
                    o.y += xsT[(c+1)*NTH + p];
                    o.z += xsT[(c+2)*NTH + p];
                    o.w += xsT[(c+3)*NTH + p];
                }
                *(float4*)(op + c) = o;
                if (ACC) {
                    csum[q*4+0] += o.x; csum[q*4+1] += o.y;
                    csum[q*4+2] += o.z; csum[q*4+3] += o.w;
                }
            }
        }
        if (ACC) {
            float* red = Ws;   // reuse (done with weights)
            #pragma unroll
            for (int q = 0; q < 4; q++) {
                int c = q*16 + ng*4;
                *(float4*)(red + mg*64 + c) =
                    make_float4(csum[q*4], csum[q*4+1], csum[q*4+2], csum[q*4+3]);
            }
        }
    }
    if (ACC) {
        __syncthreads();
        if (tid < 64) {
            float s = 0.f;
            #pragma unroll 4
            for (int m = 0; m < 68; m++) s += Ws[m*64 + tid];
            g_part[((size_t)b*NT + blockIdx.x)*64 + tid] = s;
        }
    }
}

// ---------------------------------------------------------------------------
// Final: mean-pool (from partials) -> LayerNorm -> FC
// ---------------------------------------------------------------------------
__global__ void finalize_kernel(const float* __restrict__ lns, const float* __restrict__ lnb,
                                const float* __restrict__ fcw, const float* __restrict__ fcb,
                                float* __restrict__ out)
{
    int b = blockIdx.x;
    int c = threadIdx.x;   // 64 threads
    float s = 0.f;
    const float* pp = g_part + (size_t)b * NT * 64;
    for (int t = 0; t < NT; t++) s += pp[t*64 + c];
    s *= (1.f / ((float)T_LEN * (float)KP));

    __shared__ float red[64];
    __shared__ float sf[64];
    red[c] = s; __syncthreads();
    for (int off = 32; off; off >>= 1) { if (c < off) red[c] += red[c+off]; __syncthreads(); }
    float mu = red[0] * (1.f/64.f);
    __syncthreads();
    float d = s - mu;
    red[c] = d * d; __syncthreads();
    for (int off = 32; off; off >>= 1) { if (c < off) red[c] += red[c+off]; __syncthreads(); }
    float var = red[0] * (1.f/64.f);
    float f = d * rsqrtf(var + 1e-5f) * lns[c] + lnb[c];
    sf[c] = f; __syncthreads();
    if (c < NCLS) {
        float o = fcb[c];
        #pragma unroll
        for (int i = 0; i < 64; i++) o += sf[i] * fcw[i*NCLS + c];
        out[b*NCLS + c] = o;
    }
}

static inline size_t smem_bytes(int CIN, int D) {
    int NTH = (TILE_T + 2*D) * KP;
    int XS  = ((CIN*NTH + 3) & ~3);
    return (size_t)(XS + 3*CIN*HID + ROWS*ZW + 292 + 64) * sizeof(float);
}

extern "C" void kernel_launch(void* const* d_in, const int* in_sizes, int n_in,
                              void* d_out, int out_size)
{
    const float* kpts = (const float*)d_in[0];
    const float* adj  = (const float*)d_in[1];
    const float* gw0  = (const float*)d_in[2];
    const float* gw1  = (const float*)d_in[3];
    const float* gw2  = (const float*)d_in[4];
    const float* tcn  = (const float*)d_in[5];
    const float* bs   = (const float*)d_in[6];
    const float* bb   = (const float*)d_in[7];
    const float* bm   = (const float*)d_in[8];
    const float* bv   = (const float*)d_in[9];
    const float* lns  = (const float*)d_in[10];
    const float* lnb  = (const float*)d_in[11];
    const float* fcw  = (const float*)d_in[12];
    const float* fcb  = (const float*)d_in[13];
    float* out = (float*)d_out;

    float *buf0, *buf1;
    cudaGetSymbolAddress((void**)&buf0, g_buf0);
    cudaGetSymbolAddress((void**)&buf1, g_buf1);

    size_t s0 = smem_bytes(3, 1);
    size_t s1 = smem_bytes(64, 1);
    size_t s2 = smem_bytes(64, 2);
    cudaFuncSetAttribute(stblock<3,1,false,false>, cudaFuncAttributeMaxDynamicSharedMemorySize, (int)s0);
    cudaFuncSetAttribute(stblock<64,1,true,false>, cudaFuncAttributeMaxDynamicSharedMemorySize, (int)s1);
    cudaFuncSetAttribute(stblock<64,2,true,true>,  cudaFuncAttributeMaxDynamicSharedMemorySize, (int)s2);

    prep_kernel<<<dim3(3,3), 64>>>(gw0, gw1, gw2, tcn, bs, bb, bm, bv);

    dim3 grid(NT, B_SZ);
    stblock<3,1,false,false><<<grid, 288, s0>>>(kpts, buf0, adj, 0);
    stblock<64,1,true,false><<<grid, 288, s1>>>(buf0, buf1, adj, 1);
    stblock<64,2,true,true> <<<grid, 288, s2>>>(buf1, buf0, adj, 2);

    finalize_kernel<<<B_SZ, 64>>>(lns, lnb, fcw, fcb, out);
}

// round 3
// speedup vs baseline: 1.3546x; 1.3546x over previous
#include <cuda_runtime.h>
#include <cuda_bf16.h>

#define T_LEN 2048
#define KP    17
#define KPAD  18
#define HID   64
#define B_SZ  32
#define NCLS  10
#define TILE_T 16
#define NT    (T_LEN / TILE_T)     // 128

typedef unsigned long long ull;

// Scratch (allocation-free rule: __device__ globals)
__device__ float g_buf0[(size_t)B_SZ * T_LEN * KP * HID];
__device__ float g_buf1[(size_t)B_SZ * T_LEN * KP * HID];
__device__ float g_Wf[3][3 * HID * HID];   // [blk][(tau*CIN + j)*64 + o]
__device__ float g_beta[3][HID];
__device__ float g_part[(size_t)B_SZ * NT * HID];

__device__ __forceinline__ void fma2(ull& d, ull a, ull b) {
    asm("fma.rn.f32x2 %0, %1, %2, %3;" : "=l"(d) : "l"(a), "l"(b), "l"(d));
}
__device__ __forceinline__ ull pack2(float x, float y) {
    ull r;
    asm("mov.b64 %0, {%1, %2};" : "=l"(r) : "f"(x), "f"(y));
    return r;
}
__device__ __forceinline__ float2 unpack2(ull v) {
    float2 r;
    asm("mov.b64 {%0, %1}, %2;" : "=f"(r.x), "=f"(r.y) : "l"(v));
    return r;
}

// ---------------------------------------------------------------------------
// Wf[blk][tau][j][o] = (sum_i gw[j,i] * tw[o,i,tau]) * bn_inv[o]
// beta[blk][o] = bb - bs*bm/sqrt(bv+eps)
// ---------------------------------------------------------------------------
__global__ void prep_kernel(const float* __restrict__ gw0, const float* __restrict__ gw1,
                            const float* __restrict__ gw2, const float* __restrict__ tcn,
                            const float* __restrict__ bs, const float* __restrict__ bb,
                            const float* __restrict__ bm, const float* __restrict__ bv)
{
    int blk = blockIdx.x;      // 0..2
    int tau = blockIdx.y;      // 0..2
    int o   = threadIdx.x;     // 0..63
    const float* gw = (blk == 0) ? gw0 : ((blk == 1) ? gw1 : gw2);
    int CIN = (blk == 0) ? 3 : 64;
    float rstd = rsqrtf(bv[blk*64 + o] + 1e-5f);
    float inv  = bs[blk*64 + o] * rstd;
    if (tau == 0)
        g_beta[blk][o] = bb[blk*64 + o] - bs[blk*64 + o] * bm[blk*64 + o] * rstd;
    const float* tw = tcn + (size_t)blk * HID * HID * 3;   // [o][i][tau]
    for (int j = 0; j < CIN; j++) {
        float s = 0.f;
        for (int i = 0; i < HID; i++)
            s += gw[j*HID + i] * tw[(o*HID + i)*3 + tau];
        g_Wf[blk][(tau*CIN + j)*HID + o] = s * inv;
    }
}

// ---------------------------------------------------------------------------
// Fused ST-GCN block:
//  premix xg = A*x into smem (graph conv commuted to input side),
//  temporal/channel GEMM with f32x2 packed FFMA (rows pairwise in lanes),
//  epilogue: BN bias + ReLU + residual (re-read x from gmem) + optional pool.
// Padded planes: 18 slots per t (slot 17 zero, outputs there discarded).
// ---------------------------------------------------------------------------
template<int CIN, int D, bool RES, bool ACC>
__global__ __launch_bounds__(288, 2)
void stblock(const float* __restrict__ xin, float* __restrict__ yout,
             const float* __restrict__ adjg, int blk)
{
    constexpr int NTT  = TILE_T + 2*D;          // halo'd t rows
    constexpr int NTHP = NTT * KPAD;            // padded plane count
    constexpr int XW   = NTHP + 2;              // even stride per channel
    constexpr int XS   = ((CIN*XW + 3) & ~3);   // 16B-align the Ws region
    constexpr int WS_SZ = (CIN == 64) ? (HID*HID) : (3*CIN*HID);

    extern __shared__ float sm[];
    float* xg   = sm;                    // [CIN][XW] graph-premixed x (padded planes)
    float* Ws   = sm + XS;               // staged weights (per-tau for CIN=64)
    float* sadj = Ws + WS_SZ;            // [17][18], col 17 = 0 (+2 pad)
    float* sbet = sadj + 308;            // [64]

    const int tid = threadIdx.x;
    const int b   = blockIdx.y;
    const int t0  = blockIdx.x * TILE_T;

    for (int u = tid; u < KP*KPAD; u += 288) {
        int v = u / KPAD, k = u - v*KPAD;
        sadj[u] = (k < KP) ? adjg[v*KP + k] : 0.f;
    }
    if (tid < HID) sbet[tid] = g_beta[blk][tid];
    if (CIN == 3) {
        for (int u = tid; u < WS_SZ; u += 288) Ws[u] = g_Wf[blk][u];
    }
    __syncthreads();

    // ---- premix: xg[c][tl*18+k] = sum_v x[tg][v][c] * adj[v][k]  (0 if OOB) ----
    const float* xb = xin + (size_t)b * T_LEN * KP * CIN;
    for (int u = tid; u < NTT * CIN; u += 288) {
        int tl = u / CIN, c = u - tl*CIN;       // consecutive tid -> consecutive c
        int tg = t0 + tl - D;
        float raw[KP];
        if (tg >= 0 && tg < T_LEN) {
            const float* xr = xb + (size_t)tg * KP * CIN + c;
            #pragma unroll
            for (int v = 0; v < KP; v++) raw[v] = __ldg(xr + v*CIN);
        } else {
            #pragma unroll
            for (int v = 0; v < KP; v++) raw[v] = 0.f;
        }
        ull s2[KPAD/2];
        #pragma unroll
        for (int p = 0; p < KPAD/2; p++) s2[p] = 0ull;
        #pragma unroll
        for (int v = 0; v < KP; v++) {
            ull rd = pack2(raw[v], raw[v]);
            const ull* ap = (const ull*)(sadj + v*KPAD);
            #pragma unroll
            for (int p = 0; p < KPAD/2; p++) fma2(s2[p], rd, ap[p]);
        }
        ull* xo = (ull*)(xg + c*XW + tl*KPAD);
        #pragma unroll
        for (int p = 0; p < KPAD/2; p++) xo[p] = s2[p];
    }
    __syncthreads();

    const int cg = tid & 7;          // col group (8 cols each)
    const int rg = tid >> 3;         // padded-row group 0..35
    const int r0 = rg * 8;
    const float* wf = g_Wf[blk];

    ull acc[4][8];                   // [rowpair][col], rows packed in f32x2 lanes
    #pragma unroll
    for (int q = 0; q < 4; q++)
        #pragma unroll
        for (int p = 0; p < 8; p++) acc[q][p] = 0ull;

    #pragma unroll
    for (int tau = 0; tau < 3; tau++) {
        const float* wsrc;
        if (CIN == 64) {
            if (tau > 0) __syncthreads();
            const float4* src = (const float4*)(wf + tau*HID*HID);
            for (int u = tid; u < HID*HID/4; u += 288) ((float4*)Ws)[u] = src[u];
            __syncthreads();
            wsrc = Ws;
        } else {
            wsrc = Ws + tau*CIN*HID;
        }
        const float* xpb = xg + tau*(KPAD*D) + r0;
        #pragma unroll 8
        for (int j = 0; j < CIN; j++) {
            const ull* xp = (const ull*)(xpb + j*XW);
            ull x0 = xp[0], x1 = xp[1], x2 = xp[2], x3 = xp[3];
            const float* wr = wsrc + j*HID + cg*8;
            float4 wa = *(const float4*)(wr);
            float4 wb = *(const float4*)(wr + 4);
            ull wd[8];
            wd[0] = pack2(wa.x, wa.x); wd[1] = pack2(wa.y, wa.y);
            wd[2] = pack2(wa.z, wa.z); wd[3] = pack2(wa.w, wa.w);
            wd[4] = pack2(wb.x, wb.x); wd[5] = pack2(wb.y, wb.y);
            wd[6] = pack2(wb.z, wb.z); wd[7] = pack2(wb.w, wb.w);
            #pragma unroll
            for (int p = 0; p < 8; p++) {
                fma2(acc[0][p], x0, wd[p]);
                fma2(acc[1][p], x1, wd[p]);
                fma2(acc[2][p], x2, wd[p]);
                fma2(acc[3][p], x3, wd[p]);
            }
        }
    }
    __syncthreads();   // Ws reads done (red reuse below); uniform

    // ---- epilogue: bias + relu + residual + store (+pool) ----
    const float4 bA = *(const float4*)(sbet + cg*8);
    const float4 bB = *(const float4*)(sbet + cg*8 + 4);
    float csum[8];
    if (ACC) {
        #pragma unroll
        for (int p = 0; p < 8; p++) csum[p] = 0.f;
    }
    #pragma unroll
    for (int q = 0; q < 4; q++) {
        float vr[2][8];
        #pragma unroll
        for (int p = 0; p < 8; p++) {
            float2 u2 = unpack2(acc[q][p]);
            vr[0][p] = u2.x; vr[1][p] = u2.y;
        }
        #pragma unroll
        for (int h = 0; h < 2; h++) {
            int r  = r0 + 2*q + h;
            int tl = r / KPAD;
            int kk = r - tl*KPAD;
            if (kk < KP) {
                size_t base = (((size_t)b*T_LEN + (t0 + tl))*KP + kk)*HID + cg*8;
                float4 o0, o1;
                o0.x = fmaxf(vr[h][0] + bA.x, 0.f);
                o0.y = fmaxf(vr[h][1] + bA.y, 0.f);
                o0.z = fmaxf(vr[h][2] + bA.z, 0.f);
                o0.w = fmaxf(vr[h][3] + bA.w, 0.f);
                o1.x = fmaxf(vr[h][4] + bB.x, 0.f);
                o1.y = fmaxf(vr[h][5] + bB.y, 0.f);
                o1.z = fmaxf(vr[h][6] + bB.z, 0.f);
                o1.w = fmaxf(vr[h][7] + bB.w, 0.f);
                if (RES) {
                    float4 x0 = *(const float4*)(xin + base);
                    float4 x1 = *(const float4*)(xin + base + 4);
                    o0.x += x0.x; o0.y += x0.y; o0.z += x0.z; o0.w += x0.w;
                    o1.x += x1.x; o1.y += x1.y; o1.z += x1.z; o1.w += x1.w;
                }
                *(float4*)(yout + base)     = o0;
                *(float4*)(yout + base + 4) = o1;
                if (ACC) {
                    csum[0] += o0.x; csum[1] += o0.y; csum[2] += o0.z; csum[3] += o0.w;
                    csum[4] += o1.x; csum[5] += o1.y; csum[6] += o1.z; csum[7] += o1.w;
                }
            }
        }
    }
    if (ACC) {
        float* red = Ws;    // reuse; 36*64 = 2304 <= 4096 floats
        *(float4*)(red + rg*64 + cg*8)     = make_float4(csum[0], csum[1], csum[2], csum[3]);
        *(float4*)(red + rg*64 + cg*8 + 4) = make_float4(csum[4], csum[5], csum[6], csum[7]);
        __syncthreads();
        if (tid < 64) {
            float s = 0.f;
            #pragma unroll 4
            for (int m = 0; m < 36; m++) s += red[m*64 + tid];
            g_part[((size_t)b*NT + blockIdx.x)*64 + tid] = s;
        }
    }
}

// ---------------------------------------------------------------------------
// Final: mean-pool (from partials) -> LayerNorm -> FC
// ---------------------------------------------------------------------------
__global__ void finalize_kernel(const float* __restrict__ lns, const float* __restrict__ lnb,
                                const float* __restrict__ fcw, const float* __restrict__ fcb,
                                float* __restrict__ out)
{
    int b = blockIdx.x;
    int c = threadIdx.x;   // 64 threads
    float s = 0.f;
    const float* pp = g_part + (size_t)b * NT * 64;
    for (int t = 0; t < NT; t++) s += pp[t*64 + c];
    s *= (1.f / ((float)T_LEN * (float)KP));

    __shared__ float red[64];
    __shared__ float sf[64];
    red[c] = s; __syncthreads();
    for (int off = 32; off; off >>= 1) { if (c < off) red[c] += red[c+off]; __syncthreads(); }
    float mu = red[0] * (1.f/64.f);
    __syncthreads();
    float d = s - mu;
    red[c] = d * d; __syncthreads();
    for (int off = 32; off; off >>= 1) { if (c < off) red[c] += red[c+off]; __syncthreads(); }
    float var = red[0] * (1.f/64.f);
    float f = d * rsqrtf(var + 1e-5f) * lns[c] + lnb[c];
    sf[c] = f; __syncthreads();
    if (c < NCLS) {
        float o = fcb[c];
        #pragma unroll
        for (int i = 0; i < 64; i++) o += sf[i] * fcw[i*NCLS + c];
        out[b*NCLS + c] = o;
    }
}

static inline size_t smem_bytes(int CIN, int D) {
    int NTT = TILE_T + 2*D;
    int XW  = NTT*KPAD + 2;
    int XS  = ((CIN*XW + 3) & ~3);
    int WS  = (CIN == 64) ? (HID*HID) : (3*CIN*HID);
    return (size_t)(XS + WS + 308 + 64) * sizeof(float);
}

extern "C" void kernel_launch(void* const* d_in, const int* in_sizes, int n_in,
                              void* d_out, int out_size)
{
    const float* kpts = (const float*)d_in[0];
    const float* adj  = (const float*)d_in[1];
    const float* gw0  = (const float*)d_in[2];
    const float* gw1  = (const float*)d_in[3];
    const float* gw2  = (const float*)d_in[4];
    const float* tcn  = (const float*)d_in[5];
    const float* bs   = (const float*)d_in[6];
    const float* bb   = (const float*)d_in[7];
    const float* bm   = (const float*)d_in[8];
    const float* bv   = (const float*)d_in[9];
    const float* lns  = (const float*)d_in[10];
    const float* lnb  = (const float*)d_in[11];
    const float* fcw  = (const float*)d_in[12];
    const float* fcb  = (const float*)d_in[13];
    float* out = (float*)d_out;

    float *buf0, *buf1;
    cudaGetSymbolAddress((void**)&buf0, g_buf0);
    cudaGetSymbolAddress((void**)&buf1, g_buf1);

    size_t s0 = smem_bytes(3, 1);
    size_t s1 = smem_bytes(64, 1);
    size_t s2 = smem_bytes(64, 2);
    cudaFuncSetAttribute(stblock<3,1,false,false>, cudaFuncAttributeMaxDynamicSharedMemorySize, (int)s0);
    cudaFuncSetAttribute(stblock<64,1,true,false>, cudaFuncAttributeMaxDynamicSharedMemorySize, (int)s1);
    cudaFuncSetAttribute(stblock<64,2,true,true>,  cudaFuncAttributeMaxDynamicSharedMemorySize, (int)s2);

    prep_kernel<<<dim3(3,3), 64>>>(gw0, gw1, gw2, tcn, bs, bb, bm, bv);

    dim3 grid(NT, B_SZ);
    stblock<3,1,false,false><<<grid, 288, s0>>>(kpts, buf0, adj, 0);
    stblock<64,1,true,false><<<grid, 288, s1>>>(buf0, buf1, adj, 1);
    stblock<64,2,true,true> <<<grid, 288, s2>>>(buf1, buf0, adj, 2);

    finalize_kernel<<<B_SZ, 64>>>(lns, lnb, fcw, fcb, out);
}